// round 16
// baseline (speedup 1.0000x reference)
#include <cuda_runtime.h>
#include <cuda_bf16.h>
#include <cstdint>

// GMM log-likelihood, N=524288, K=32, D=8 — bf16 mma.sync m16n8k16, round 16:
// round-15 fused kernel with a fully CONFLICT-FREE XOR-swizzled A staging.
// Old 224B layout had 2-way conflicts on BOTH STS.128 and LDS.128 (~20K
// smem cycles/SM, L1=57%). New: 256B/point, physical chunk = c ^ rot(row&7),
// rot(p) = ((p&1)<<2)|((p>>1)&3). Verified by phase enumeration:
//   STS.128: c ^ rot(l) bijective per 8-lane phase -> 1-way
//   LDS.128: r ^ rot(g) -> {r} u {r^4} distinct -> 1-way (hi & lo, all rows)
//   LDS.64 : step-2 pairs in chunks 4/6 (lo 12/14) -> 1-way
// Logical chunk contents identical to the verified round-12/13 layout.
//
// Math: 48 padded features [x_i*x_j (i<=j), x_i, 1]; coefs from P = W^T W;
// log2 domain, max const folded; 3-term bf16 product A=[F1 F1 F2] x
// B=[C1 C2 C1] over K=144. Per warp-iter: 12 STS.128 + 16 LDS + 72 HMMA.

typedef unsigned int u32;
typedef unsigned short u16;

#define TPB    128
#define GRIDN  456             // 152 SMs x 3 CTAs
#define TW     (GRIDN * 4)     // 1824 warps
#define NI     16384           // warp-iterations (x32 points = 524288)

#define PSTRIDE_B 256          // 16 chunk slots per point (12 used)
#define AWARP_B   (32 * PSTRIDE_B)       // 8192 B
#define BIMG_B    6400                   // B image region (6148 used), 256-aligned
#define SMEM_TOTAL (256 + BIMG_B + 4 * AWARP_B)   // 39424 B (256 = align slack)

// ---------------- helpers ----------------
__device__ __forceinline__ u32 smem_u32(const void* p) {
    u32 a; asm("{ .reg .u64 t; cvta.to.shared.u64 t, %1; cvt.u32.u64 %0, t; }"
               : "=r"(a) : "l"(p)); return a;
}
__device__ __forceinline__ float ex2f(float x) {
    float r; asm("ex2.approx.f32 %0, %1;" : "=f"(r) : "f"(x)); return r;
}
// pack top16(a), top16(b) -> {hi16(b):hi16(a)}
__device__ __forceinline__ u32 prmt7632(float a, float b) {
    u32 r; asm("prmt.b32 %0, %1, %2, 0x7632;"
               : "=r"(r) : "r"(__float_as_uint(a)), "r"(__float_as_uint(b)));
    return r;
}
__device__ __forceinline__ void sts128(u32 addr, u32 a, u32 b, u32 c, u32 d) {
    asm volatile("st.shared.v4.b32 [%0], {%1, %2, %3, %4};"
                 :: "r"(addr), "r"(a), "r"(b), "r"(c), "r"(d) : "memory");
}
__device__ __forceinline__ void lds128(u32& a, u32& b, u32& c, u32& d, u32 addr) {
    asm volatile("ld.shared.v4.b32 {%0, %1, %2, %3}, [%4];"
                 : "=r"(a), "=r"(b), "=r"(c), "=r"(d) : "r"(addr));
}
__device__ __forceinline__ void lds64(u32& a, u32& b, u32 addr) {
    asm volatile("ld.shared.v2.b32 {%0, %1}, [%2];" : "=r"(a), "=r"(b) : "r"(addr));
}
__device__ __forceinline__ void mma_bf16(float& d0, float& d1, float& d2, float& d3,
                                         u32 a0, u32 a1, u32 a2, u32 a3,
                                         u32 b0, u32 b1) {
    asm volatile(
        "mma.sync.aligned.m16n8k16.row.col.f32.bf16.bf16.f32 "
        "{%0,%1,%2,%3}, {%4,%5,%6,%7}, {%8,%9}, {%0,%1,%2,%3};"
        : "+f"(d0), "+f"(d1), "+f"(d2), "+f"(d3)
        : "r"(a0), "r"(a1), "r"(a2), "r"(a3), "r"(b0), "r"(b1));
}

__device__ __forceinline__ int tri(int i, int j) { return i * (i + 1) / 2 + j; }
__device__ __forceinline__ u32 rot3(u32 p) { return ((p & 1u) << 2) | ((p >> 1) & 3u); }

// feature c — compile-time literal under full unroll (branch chain folds).
__device__ __forceinline__ float fv(const float xx[8], int c) {
    const int FI_[36] = {0,0,0,0,0,0,0,0, 1,1,1,1,1,1,1, 2,2,2,2,2,2,
                         3,3,3,3,3, 4,4,4,4, 5,5,5, 6,6, 7};
    const int FJ_[36] = {0,1,2,3,4,5,6,7, 1,2,3,4,5,6,7, 2,3,4,5,6,7,
                         3,4,5,6,7, 4,5,6,7, 5,6,7, 6,7, 7};
    if (c >= 45) return 0.0f;
    if (c == 44) return 1.0f;
    if (c >= 36) return xx[c - 36];
    return xx[FI_[c]] * xx[FJ_[c]];
}

__device__ __forceinline__ u16 bf16rn(float f) {
    return __bfloat16_as_ushort(__float2bfloat16(f));
}

// ---------------- fused main ----------------
__global__ void __launch_bounds__(TPB, 3)
gmm_main(const float* __restrict__ x,
         const float* __restrict__ pi,
         const float* __restrict__ means,
         const float* __restrict__ cv,
         float* __restrict__ out) {
    extern __shared__ __align__(16) char smem[];
    // round base up to 256B so base ^ imm address folding is exact
    const u32 raw = smem_u32(smem);
    const u32 sb0 = (raw + 255u) & ~255u;
    char* smc = smem + (sb0 - raw);
    uint2* bimg = reinterpret_cast<uint2*>(smc);           // 768 uint2
    float* mcp  = reinterpret_cast<float*>(smc + 6144);

    const int tid = threadIdx.x;
    const int wid = tid >> 5;
    const int lane = tid & 31;
    const u32 sa = sb0 + BIMG_B + (u32)wid * AWARP_B;      // 256-aligned

    const int g = lane >> 2;      // mma row group 0..7
    const int r = lane & 3;       // thread-in-group 0..3

    int it = blockIdx.x * 4 + wid;

    // first x load in flight while warp 0 preps
    float4 v0, v1;
    {
        const float4* px = reinterpret_cast<const float4*>(x + (size_t)(it * 32 + lane) * 8);
        v0 = px[0]; v1 = px[1];
    }

    // ---- prep: warp 0, one lane per component (register-light) ----
    if (tid < 32) {
        const int k = lane;

        float Wt[36];                       // L, inverted in place
#pragma unroll
        for (int i = 0; i < 8; i++)
#pragma unroll
            for (int j = 0; j <= i; j++)
                Wt[tri(i, j)] = cv[k * 64 + i * 8 + j];

        float logdet = 0.0f;
#pragma unroll
        for (int i = 0; i < 8; i++) logdet += __logf(fabsf(Wt[tri(i, i)]));
        logdet *= 2.0f;

#pragma unroll
        for (int c = 0; c < 8; c++) {
            float dc = __fdividef(1.0f, Wt[tri(c, c)]);
            Wt[tri(c, c)] = dc;
#pragma unroll
            for (int i = c + 1; i < 8; i++) {
                float t = 0.0f;
#pragma unroll
                for (int p = c; p < i; p++) t += Wt[tri(i, p)] * Wt[tri(p, c)];
                Wt[tri(i, c)] = -__fdividef(t, Wt[tri(i, i)]);
            }
        }

        float mu[8], zm[8], h[8];
#pragma unroll
        for (int j = 0; j < 8; j++) mu[j] = means[k * 8 + j];
        float q0 = 0.0f;
#pragma unroll
        for (int m = 0; m < 8; m++) {
            float t = 0.0f;
#pragma unroll
            for (int j = 0; j <= m; j++) t += Wt[tri(m, j)] * mu[j];
            zm[m] = t; q0 += t * t;
        }
#pragma unroll
        for (int i = 0; i < 8; i++) {
            float t = 0.0f;
#pragma unroll
            for (int m = i; m < 8; m++) t += Wt[tri(m, i)] * zm[m];
            h[i] = t;
        }

        float pk = pi[k];
        float mx = pk;
#pragma unroll
        for (int o = 16; o; o >>= 1) mx = fmaxf(mx, __shfl_xor_sync(0xffffffffu, mx, o));
        float se = __expf(pk - mx);
#pragma unroll
        for (int o = 16; o; o >>= 1) se += __shfl_xor_sync(0xffffffffu, se, o);
        float lp = pk - mx - __logf(se);

        const float LOG2E = 1.4426950408889634f;
        const float LOG_2PI = 1.8378770664093453f;
        const float s2 = 0.5f * LOG2E;
        float cst2 = (lp - 0.5f * (8.0f * LOG_2PI + logdet)) * LOG2E;

        float M2 = cst2;
#pragma unroll
        for (int o = 16; o; o >>= 1) M2 = fmaxf(M2, __shfl_xor_sync(0xffffffffu, M2, o));

        float Cc[48];
        int idx = 0;
#pragma unroll
        for (int i = 0; i < 8; i++)
#pragma unroll
            for (int j = i; j < 8; j++) {
                float pm = 0.0f;
#pragma unroll
                for (int m = j; m < 8; m++) pm += Wt[tri(m, i)] * Wt[tri(m, j)];
                Cc[idx++] = (i == j) ? -s2 * pm : -2.0f * s2 * pm;
            }
#pragma unroll
        for (int i = 0; i < 8; i++) Cc[36 + i] = 2.0f * s2 * h[i];
        Cc[44] = cst2 - M2 - s2 * q0;
        Cc[45] = 0.0f; Cc[46] = 0.0f; Cc[47] = 0.0f;

#pragma unroll
        for (int cc = 0; cc < 2; cc++)
#pragma unroll
            for (int s = 0; s < 3; s++)
#pragma unroll
                for (int rr = 0; rr < 4; rr++) {
                    const int fb = 16 * s + 2 * rr;
                    u16 e0, e1, e2, e3;
                    if (cc == 0) {
                        e0 = bf16rn(Cc[fb]);     e1 = bf16rn(Cc[fb + 1]);
                        e2 = bf16rn(Cc[fb + 8]); e3 = bf16rn(Cc[fb + 9]);
                    } else {
                        e0 = bf16rn(Cc[fb]     - __bfloat162float(__float2bfloat16(Cc[fb])));
                        e1 = bf16rn(Cc[fb + 1] - __bfloat162float(__float2bfloat16(Cc[fb + 1])));
                        e2 = bf16rn(Cc[fb + 8] - __bfloat162float(__float2bfloat16(Cc[fb + 8])));
                        e3 = bf16rn(Cc[fb + 9] - __bfloat162float(__float2bfloat16(Cc[fb + 9])));
                    }
                    u32 b0 = (u32)e0 | ((u32)e1 << 16);
                    u32 b1 = (u32)e2 | ((u32)e3 << 16);
                    bimg[(cc * 3 + s) * 128 + rr * 32 + k] = make_uint2(b0, b1);
                }
        if (k == 0) *mcp = M2 * 0.69314718055994531f;
    }
    __syncthreads();

    // B fragments -> registers
    u32 bf[48];
#pragma unroll
    for (int q = 0; q < 6; q++)
#pragma unroll
        for (int nt = 0; nt < 4; nt++) {
            uint2 v = bimg[q * 128 + r * 32 + nt * 8 + g];
            bf[(q * 4 + nt) * 2]     = v.x;
            bf[(q * 4 + nt) * 2 + 1] = v.y;
        }
    const float Mc = *mcp;

    // swizzled addresses
    const u32 arow = sa + (u32)lane * PSTRIDE_B + rot3((u32)lane & 7u) * 16u;  // store base
    const u32 rg16 = rot3((u32)g) * 16u;
    const u32 rA  = sa + (u32)g * PSTRIDE_B + rg16;     // tile A row g
    const u32 rA8 = rA + 8 * PSTRIDE_B;                 // row g+8
    const u32 rB  = rA + 16 * PSTRIDE_B;                // tile B rows
    const u32 rB8 = rA + 24 * PSTRIDE_B;
    const u32 ofsA = (u32)r * 16u;                                   // hi steps 0,1 chunk
    const u32 ofs2 = 64u + ((u32)(r >> 1)) * 32u + ((u32)(r & 1)) * 8u;  // hi step 2
    const u32 ofsAl = ofsA | 128u;                                   // lo mirrors
    const u32 ofs2l = ofs2 | 128u;

#pragma unroll 1
    while (it < NI) {
        const int base = it * 32;
        const int in = it + TW;
        float xx[8] = {v0.x, v0.y, v0.z, v0.w, v1.x, v1.y, v1.z, v1.w};

        // ---- stage one full point per lane (swizzled chunk placement) ----
        {
            u32 H[24], Lo[24];
#pragma unroll
            for (int p = 0; p < 24; p++) {
                float f0 = fv(xx, 2 * p), f1 = fv(xx, 2 * p + 1);
                H[p] = prmt7632(f0, f1);
                float l0 = f0 - __uint_as_float(__float_as_uint(f0) & 0xFFFF0000u);
                float l1 = f1 - __uint_as_float(__float_as_uint(f1) & 0xFFFF0000u);
                Lo[p] = prmt7632(l0, l1);
            }
#pragma unroll
            for (int rv = 0; rv < 4; rv++)
                sts128(arow ^ (u32)(rv * 16), H[rv], H[rv + 4], H[8 + rv], H[12 + rv]);
            sts128(arow ^ 64u, H[16], H[20], H[17], H[21]);     // chunk 4
            sts128(arow ^ 96u, H[18], H[22], H[19], H[23]);     // chunk 6
#pragma unroll
            for (int rv = 0; rv < 4; rv++)
                sts128(arow ^ (u32)(128 + rv * 16), Lo[rv], Lo[rv + 4], Lo[8 + rv], Lo[12 + rv]);
            sts128(arow ^ 192u, Lo[16], Lo[20], Lo[17], Lo[21]); // chunk 12
            sts128(arow ^ 224u, Lo[18], Lo[22], Lo[19], Lo[23]); // chunk 14
        }
        __syncwarp();

        if (in < NI) {
            const float4* px = reinterpret_cast<const float4*>(x + (size_t)(in * 32 + lane) * 8);
            v0 = px[0]; v1 = px[1];
        }

        // ---- A fragments for both tiles ----
        u32 u0,u1,u2,u3,u4,u5, va0,va1,va2,va3,va4,va5;
        u32 w0,w1,w2,w3,w4,w5, z0,z1,z2,z3,z4,z5;
        lds128(u0, u1, u2, u3, rA ^ ofsA);
        lds128(va0, va1, va2, va3, rA8 ^ ofsA);
        lds64(u4, u5, rA ^ ofs2);
        lds64(va4, va5, rA8 ^ ofs2);
        lds128(w0, w1, w2, w3, rA ^ ofsAl);
        lds128(z0, z1, z2, z3, rA8 ^ ofsAl);
        lds64(w4, w5, rA ^ ofs2l);
        lds64(z4, z5, rA8 ^ ofs2l);

        u32 m0,m1,m2,m3,m4,m5, n0,n1,n2,n3,n4,n5;
        u32 o0,o1,o2,o3,o4,o5, q0,q1,q2,q3,q4,q5;
        lds128(m0, m1, m2, m3, rB ^ ofsA);
        lds128(n0, n1, n2, n3, rB8 ^ ofsA);
        lds64(m4, m5, rB ^ ofs2);
        lds64(n4, n5, rB8 ^ ofs2);
        lds128(o0, o1, o2, o3, rB ^ ofsAl);
        lds128(q0, q1, q2, q3, rB8 ^ ofsAl);
        lds64(o4, o5, rB ^ ofs2l);
        lds64(q4, q5, rB8 ^ ofs2l);

        float dA[4][4], dB[4][4];
#pragma unroll
        for (int nt = 0; nt < 4; nt++)
#pragma unroll
            for (int e = 0; e < 4; e++) { dA[nt][e] = 0.0f; dB[nt][e] = 0.0f; }

#define MMA_STEP(D, A0, A1, A2, A3, Q)                                        \
        {                                                                     \
            _Pragma("unroll")                                                 \
            for (int nt = 0; nt < 4; nt++)                                    \
                mma_bf16(D[nt][0], D[nt][1], D[nt][2], D[nt][3],              \
                         A0, A1, A2, A3,                                      \
                         bf[((Q) * 4 + nt) * 2], bf[((Q) * 4 + nt) * 2 + 1]); \
        }
        MMA_STEP(dA, u0, va0, u1, va1, 0)
        MMA_STEP(dB, m0, n0, m1, n1, 0)
        MMA_STEP(dA, u0, va0, u1, va1, 3)
        MMA_STEP(dB, m0, n0, m1, n1, 3)
        MMA_STEP(dA, w0, z0, w1, z1, 0)
        MMA_STEP(dB, o0, q0, o1, q1, 0)
        MMA_STEP(dA, u2, va2, u3, va3, 1)
        MMA_STEP(dB, m2, n2, m3, n3, 1)
        MMA_STEP(dA, u2, va2, u3, va3, 4)
        MMA_STEP(dB, m2, n2, m3, n3, 4)
        MMA_STEP(dA, w2, z2, w3, z3, 1)
        MMA_STEP(dB, o2, q2, o3, q3, 1)
        MMA_STEP(dA, u4, va4, u5, va5, 2)
        MMA_STEP(dB, m4, n4, m5, n5, 2)
        MMA_STEP(dA, u4, va4, u5, va5, 5)
        MMA_STEP(dB, m4, n4, m5, n5, 5)
        MMA_STEP(dA, w4, z4, w5, z5, 2)
        MMA_STEP(dB, o4, q4, o5, q5, 2)
#undef MMA_STEP

        // ---- epilogue ----
        float s0 = 0.0f, s1 = 0.0f, s2 = 0.0f, s3 = 0.0f;
#pragma unroll
        for (int nt = 0; nt < 4; nt++) {
            s0 += ex2f(dA[nt][0]) + ex2f(dA[nt][1]);
            s1 += ex2f(dA[nt][2]) + ex2f(dA[nt][3]);
            s2 += ex2f(dB[nt][0]) + ex2f(dB[nt][1]);
            s3 += ex2f(dB[nt][2]) + ex2f(dB[nt][3]);
        }
        s0 += __shfl_xor_sync(0xffffffffu, s0, 1);
        s0 += __shfl_xor_sync(0xffffffffu, s0, 2);
        s1 += __shfl_xor_sync(0xffffffffu, s1, 1);
        s1 += __shfl_xor_sync(0xffffffffu, s1, 2);
        s2 += __shfl_xor_sync(0xffffffffu, s2, 1);
        s2 += __shfl_xor_sync(0xffffffffu, s2, 2);
        s3 += __shfl_xor_sync(0xffffffffu, s3, 1);
        s3 += __shfl_xor_sync(0xffffffffu, s3, 2);
        if (r == 0) {
            out[base + g]      = Mc + __logf(fmaxf(s0, 1e-37f));
            out[base + 8 + g]  = Mc + __logf(fmaxf(s1, 1e-37f));
            out[base + 16 + g] = Mc + __logf(fmaxf(s2, 1e-37f));
            out[base + 24 + g] = Mc + __logf(fmaxf(s3, 1e-37f));
        }

        __syncwarp();
        it = in;
    }
}

extern "C" void kernel_launch(void* const* d_in, const int* in_sizes, int n_in,
                              void* d_out, int out_size) {
    const float* x     = (const float*)d_in[0];
    const float* pi    = (const float*)d_in[1];
    const float* means = (const float*)d_in[2];
    const float* cv    = (const float*)d_in[3];
    float* out = (float*)d_out;

    gmm_main<<<GRIDN, TPB, SMEM_TOTAL>>>(x, pi, means, cv, out);
}